// round 17
// baseline (speedup 1.0000x reference)
#include <cuda_runtime.h>
#include <math.h>

#define NG 4096
#define W_IMG 256
#define H_IMG 256
#define TSZ 64
#define NBLK 256           // render: 16x16 grid of 16x16-pixel blocks
#define NTHR 256
#define GPT 16             // gaussians per thread in render strip scan

#define SBLK 128           // fused sort kernel blocks (co-resident: <= 148 SMs)
#define NBG  (NG / SBLK)   // gaussians per sort block (32)

// cross-block data
__device__ unsigned long long g_key[NG];  // (z-order uint << 12) | index
__device__ volatile unsigned g_bar;       // grid barrier arrive counter
__device__ unsigned g_bar_end;            // end-of-kernel reset counter

// z-sorted outputs (consumed by render)
__device__ float4 g_sA[NG];     // mx,my,c00,c11
__device__ float2 g_sQ[NG];     // csum,op
__device__ float4 g_sR[NG];     // r,g,b,z
__device__ unsigned g_spbx[NG]; // packed bbox bytes {xmin,xmax,ymin,ymax}

// ---------------------------------------------------------------------------
// Kernel 1: fused prep + stable z-rank + scatter.
// Grid 128 x 256. Block b owns gaussians [32b, 32b+32).
//  - threads 0..31: full projection/preprocessing -> attrs in SHARED,
//    64-bit sort key -> global.
//  - grid barrier (all 128 blocks co-resident; spin by thread 0 only).
//  - stage all 4096 keys into shared; 8 threads per gaussian compute the
//    exact stable rank locally (no cross-block atomics).
//  - threads 0..31 scatter attrs from shared straight to sorted arrays.
// ---------------------------------------------------------------------------
__global__ void __launch_bounds__(256)
sort_kernel(const float* __restrict__ xyz,
            const float* __restrict__ cov_world,
            const float* __restrict__ colors,
            const float* __restrict__ opacity,
            const float* __restrict__ w2c,
            const float* __restrict__ focal,
            const float* __restrict__ pp)
{
    __shared__ unsigned long long s_keys[NG];   // 32 KB
    __shared__ float4 s_A[NBG];
    __shared__ float2 s_Q[NBG];
    __shared__ float4 s_R[NBG];
    __shared__ unsigned s_pbx[NBG];
    __shared__ int s_rank[NBG];

    const int b   = blockIdx.x;
    const int tid = threadIdx.x;

    // ---- Phase 1: prep (threads 0..31) ----
    if (tid < NBG) {
        s_rank[tid] = 0;
        const int i = b * NBG + tid;

        float R00 = w2c[0],  R01 = w2c[1],  R02 = w2c[2],  t0 = w2c[3];
        float R10 = w2c[4],  R11 = w2c[5],  R12 = w2c[6],  t1 = w2c[7];
        float R20 = w2c[8],  R21 = w2c[9],  R22 = w2c[10], t2 = w2c[11];

        float p0 = xyz[i*3+0], p1 = xyz[i*3+1], p2 = xyz[i*3+2];
        float cam0 = R00*p0 + R01*p1 + R02*p2 + t0;
        float cam1 = R10*p0 + R11*p1 + R12*p2 + t1;
        float cam2 = R20*p0 + R21*p1 + R22*p2 + t2;

        float zr = cam2;
        float z  = fmaxf(zr, 1e-6f);
        float fx = focal[0], fy = focal[1];
        float mx = fx * cam0 / z + pp[0];
        float my = fy * cam1 / z + pp[1];

        float S[3][3];
        #pragma unroll
        for (int r = 0; r < 3; r++)
            #pragma unroll
            for (int c = 0; c < 3; c++)
                S[r][c] = cov_world[i*9 + r*3 + c];

        float Rm[3][3] = {{R00,R01,R02},{R10,R11,R12},{R20,R21,R22}};
        float M[3][3], C[3][3];
        #pragma unroll
        for (int r = 0; r < 3; r++)
            #pragma unroll
            for (int c = 0; c < 3; c++)
                M[r][c] = Rm[r][0]*S[0][c] + Rm[r][1]*S[1][c] + Rm[r][2]*S[2][c];
        #pragma unroll
        for (int r = 0; r < 3; r++)
            #pragma unroll
            for (int c = 0; c < 3; c++)
                C[r][c] = M[r][0]*Rm[c][0] + M[r][1]*Rm[c][1] + M[r][2]*Rm[c][2];

        float J00 = fx / z, J02 = -fx * cam0 / (z * z);
        float J11 = fy / z, J12 = -fy * cam1 / (z * z);
        float t0v0 = J00*C[0][0] + J02*C[2][0];
        float t0v1 = J00*C[0][1] + J02*C[2][1];
        float t0v2 = J00*C[0][2] + J02*C[2][2];
        float t1v0 = J11*C[1][0] + J12*C[2][0];
        float t1v1 = J11*C[1][1] + J12*C[2][1];
        float t1v2 = J11*C[1][2] + J12*C[2][2];

        float a = t0v0*J00 + t0v2*J02 + 0.3f;
        float bb = t0v1*J11 + t0v2*J12;
        float c = t1v0*J00 + t1v2*J02;
        float d = t1v1*J11 + t1v2*J12 + 0.3f;

        float disc   = sqrtf(fmaxf(0.25f*(a-d)*(a-d) + bb*c, 0.0f));
        float maxeig = fmaxf(0.5f*(a+d) + disc, 1e-8f);
        float rraw   = 3.0f * sqrtf(maxeig);
        float radius = fminf(rraw, 64.0f);
        float det    = a*d - bb*c;
        float c00  = d / det;
        float c11  = a / det;
        float csum = (-bb - c) / det;

        float opv = opacity[i];
        bool valid = (zr > 0.1f) && (opv > 1e-4f) && (radius > 0.25f);
        valid = valid && (mx + radius >= -1.0f) && (mx - radius < (float)W_IMG + 1.0f);
        valid = valid && (my + radius >= -1.0f) && (my - radius < (float)H_IMG + 1.0f);

        // base bbox, exact reference semantics
        float radii = ceilf(radius);
        int ixmin = (int)fminf(fmaxf(floorf(mx - radii), 0.0f), 255.0f);
        int ixmax = (int)fminf(fmaxf(ceilf (mx + radii), 0.0f), 255.0f);
        int iymin = (int)fminf(fmaxf(floorf(my - radii), 0.0f), 255.0f);
        int iymax = (int)fminf(fmaxf(ceilf (my + radii), 0.0f), 255.0f);

        // Clipped radius: block bbox test must degrade to the reference
        // tile-overlap test -> expand base bbox to tile boundaries.
        if (rraw > 64.0f) {
            ixmin &= ~63; iymin &= ~63;
            ixmax |=  63; iymax |=  63;
        }

        unsigned pbx;
        if (!valid) {
            pbx = 255u | (0u << 8) | (255u << 16) | (0u << 24);   // empty
        } else {
            // opacity-aware per-axis ellipse support, intersected with base
            bool qok = (det > 0.0f) && (a > 0.0f) && (d > 0.0f);
            if (qok) {
                float tthr = fminf(9.0f, 2.0f * logf(255.0f * opv) + 0.02f);
                if (tthr <= 0.0f) {
                    ixmin = 255; ixmax = 0; iymin = 255; iymax = 0;
                } else {
                    float extx = sqrtf(tthr * a) * 1.0005f + 1.0f;
                    float exty = sqrtf(tthr * d) * 1.0005f + 1.0f;
                    int exmin = (int)fminf(fmaxf(floorf(mx - extx), 0.0f), 255.0f);
                    int exmax = (int)fminf(fmaxf(ceilf (mx + extx), 0.0f), 255.0f);
                    int eymin = (int)fminf(fmaxf(floorf(my - exty), 0.0f), 255.0f);
                    int eymax = (int)fminf(fmaxf(ceilf (my + exty), 0.0f), 255.0f);
                    ixmin = max(ixmin, exmin); ixmax = min(ixmax, exmax);
                    iymin = max(iymin, eymin); iymax = min(iymax, eymax);
                }
            }
            pbx = (unsigned)ixmin | ((unsigned)ixmax << 8) |
                  ((unsigned)iymin << 16) | ((unsigned)iymax << 24);
        }

        // order-preserving uint mapping of float z; stable via index
        unsigned zb = __float_as_uint(zr);
        unsigned zk = (zb & 0x80000000u) ? ~zb : (zb | 0x80000000u);
        g_key[i] = ((unsigned long long)zk << 12) | (unsigned)i;

        s_A[tid]   = make_float4(mx, my, c00, c11);
        s_Q[tid]   = make_float2(csum, opv);
        s_R[tid]   = make_float4(colors[i*3+0], colors[i*3+1], colors[i*3+2], zr);
        s_pbx[tid] = pbx;
    }
    __syncthreads();

    // ---- grid barrier: all keys globally visible ----
    if (tid == 0) {
        __threadfence();
        atomicAdd((unsigned*)&g_bar, 1u);
        while (g_bar < (unsigned)SBLK) { }
    }
    __syncthreads();
    __threadfence();

    // ---- Phase 2: stage all keys to shared ----
    {
        const ulonglong2* gk2 = (const ulonglong2*)g_key;
        ulonglong2* sk2 = (ulonglong2*)s_keys;
        #pragma unroll
        for (int q = 0; q < (NG / 2) / 256; q++)      // 8 iters
            sk2[tid + q * 256] = gk2[tid + q * 256];
    }
    __syncthreads();

    // ---- Phase 3: exact stable rank of this block's 32 gaussians ----
    // 8 threads per gaussian, each covering 512 keys.
    {
        const int g   = tid & (NBG - 1);
        const int seg = tid >> 5;                      // 0..7
        const unsigned long long ki = s_keys[b * NBG + g];
        const ulonglong2* k2 = (const ulonglong2*)s_keys;
        int partial = 0;
        #pragma unroll 16
        for (int j2 = seg * 256; j2 < seg * 256 + 256; j2++) {
            ulonglong2 v = k2[j2];
            partial += (v.x < ki);
            partial += (v.y < ki);
        }
        atomicAdd(&s_rank[g], partial);
    }
    __syncthreads();

    // ---- Phase 4: scatter to sorted arrays ----
    if (tid < NBG) {
        int r = s_rank[tid];
        g_sA[r]   = s_A[tid];
        g_sQ[r]   = s_Q[tid];
        g_sR[r]   = s_R[tid];
        g_spbx[r] = s_pbx[tid];
    }

    // ---- reset barrier counters for the next graph replay ----
    // Safe: a block arrives here only after passing the spin, so when the
    // LAST block resets, no block can still be spinning on g_bar.
    __syncthreads();
    if (tid == 0) {
        unsigned old = atomicAdd(&g_bar_end, 1u);
        if (old == (unsigned)SBLK - 1) {
            g_bar = 0u;
            g_bar_end = 0u;
            __threadfence();
        }
    }
}

// ---------------------------------------------------------------------------
// Kernel 2: fused bin + rasterize. One block = one 16x16 pixel block.
// Phase A: strip-scan predicates (SIMD byte compares), block scan, ordered
//          index list in shared.
// Phase B: simple composite loop; each WARP owns a compact 8x4 pixel quad
//          so the per-gaussian __any vote skips more whole-warp misses.
// ---------------------------------------------------------------------------
__global__ void __launch_bounds__(NTHR)
render_kernel(const float* __restrict__ bg, float* __restrict__ out)
{
    const int bl  = blockIdx.x;
    const int bx0 = (bl & 15) * 16;
    const int by0 = (bl >> 4) * 16;

    const int tid  = threadIdx.x;
    const int warp = tid >> 5;
    const int lane = tid & 31;

    __shared__ short s_idx[NG];
    __shared__ int wsum[8], wpre[8];
    __shared__ float4 sP[NTHR];
    __shared__ float2 sQ[NTHR];
    __shared__ float4 sR[NTHR];

    // SIMD thresholds: bytes of pbx are {xmin, xmax, ymin, ymax}
    const unsigned Tge = ((unsigned)bx0 << 8) | ((unsigned)by0 << 24);
    const unsigned Tle = (unsigned)(bx0 + 15) | (255u << 8) |
                         ((unsigned)(by0 + 15) << 16) | (255u << 24);

    // --- Phase A: predicates, 4 x LDG.128 per thread = 16 gaussians ---
    const uint4* pb4 = (const uint4*)g_spbx;
    unsigned mmask = 0;
    int lc = 0;
    #pragma unroll
    for (int q = 0; q < 4; q++) {
        uint4 p = pb4[tid * 4 + q];
        unsigned w0 = __vcmpgeu4(p.x, Tge) & __vcmpleu4(p.x, Tle);
        unsigned w1 = __vcmpgeu4(p.y, Tge) & __vcmpleu4(p.y, Tle);
        unsigned w2 = __vcmpgeu4(p.z, Tge) & __vcmpleu4(p.z, Tle);
        unsigned w3 = __vcmpgeu4(p.w, Tge) & __vcmpleu4(p.w, Tle);
        if (w0 == 0xFFFFFFFFu) { mmask |= 1u << (q*4+0); lc++; }
        if (w1 == 0xFFFFFFFFu) { mmask |= 1u << (q*4+1); lc++; }
        if (w2 == 0xFFFFFFFFu) { mmask |= 1u << (q*4+2); lc++; }
        if (w3 == 0xFFFFFFFFu) { mmask |= 1u << (q*4+3); lc++; }
    }

    // --- block-wide exclusive scan of lc ---
    int v = lc;
    #pragma unroll
    for (int d2 = 1; d2 < 32; d2 <<= 1) {
        int n = __shfl_up_sync(0xffffffffu, v, d2);
        if (lane >= d2) v += n;
    }
    if (lane == 31) wsum[warp] = v;
    __syncthreads();
    if (tid < 8) {
        int s = wsum[tid];
        #pragma unroll
        for (int d2 = 1; d2 < 8; d2 <<= 1) {
            int n = __shfl_up_sync(0xffu, s, d2);
            if (tid >= d2) s += n;
        }
        wpre[tid] = s;
    }
    __syncthreads();

    int offset = ((warp == 0) ? 0 : wpre[warp - 1]) + (v - lc);
    const int base = tid * GPT;
    unsigned mm = mmask;
    while (mm) {
        int k = __ffs(mm) - 1;
        mm &= mm - 1;
        s_idx[offset++] = (short)(base + k);
    }
    const int cnt = wpre[7];
    __syncthreads();

    // --- Phase B: composite ---
    // Warp-compact pixel mapping: each warp owns an 8x4 quad.
    const int px = bx0 + (tid & 7) + ((tid >> 5) & 1) * 8;
    const int py = by0 + ((tid >> 3) & 3) + (tid >> 6) * 4;
    const float cx = (float)px + 0.5f;
    const float cy = (float)py + 0.5f;

    float T = 1.0f;
    float accR = 0.f, accG = 0.f, accB = 0.f, acc = 0.f, dnum = 0.f;

    for (int cbase = 0; cbase < cnt; cbase += NTHR) {
        int li = cbase + tid;
        if (li < cnt) {
            int gi = s_idx[li];
            sP[tid] = g_sA[gi];
            sQ[tid] = g_sQ[gi];
            sR[tid] = g_sR[gi];
        }
        __syncthreads();

        int m = cnt - cbase; if (m > NTHR) m = NTHR;
        for (int k = 0; k < m; k++) {
            float4 P = sP[k];
            float dx = cx - P.x;
            float dy = cy - P.y;
            float2 Q = sQ[k];
            float maha = dx*dx*P.z + dy*dy*P.w + dx*dy*Q.x;
            bool hit = (maha <= 9.0f);        // NaN -> false, matches jnp.where
            if (__any_sync(0xffffffffu, hit)) {
                float alpha = fminf(__expf(-0.5f * maha) * Q.y, 0.99f);
                if (hit && alpha >= (1.0f / 255.0f)) {
                    float4 Cv = sR[k];
                    float w = T * alpha;
                    accR += w * Cv.x;
                    accG += w * Cv.y;
                    accB += w * Cv.z;
                    acc  += w;
                    dnum += w * Cv.w;
                    T *= (1.0f - alpha);
                }
            }
        }

        if (cbase + NTHR < cnt) {
            if (__syncthreads_and(T < 1e-7f)) break;
        }
    }

    float bgr = bg[0], bgg = bg[1], bgb = bg[2];
    float Rv = accR + (1.0f - acc) * bgr;
    float Gv = accG + (1.0f - acc) * bgg;
    float Bv = accB + (1.0f - acc) * bgb;
    Rv = fminf(fmaxf(Rv, 0.0f), 1.0f);
    Gv = fminf(fmaxf(Gv, 0.0f), 1.0f);
    Bv = fminf(fmaxf(Bv, 0.0f), 1.0f);
    float A = fminf(fmaxf(acc, 0.0f), 1.0f);
    float depth = (acc > 0.0f) ? (dnum / fmaxf(acc, 1e-8f)) : 0.0f;

    int o = (py * W_IMG + px) * 5;
    out[o+0] = Rv;
    out[o+1] = Gv;
    out[o+2] = Bv;
    out[o+3] = A;
    out[o+4] = depth;
}

// ---------------------------------------------------------------------------
extern "C" void kernel_launch(void* const* d_in, const int* in_sizes, int n_in,
                              void* d_out, int out_size)
{
    const float* xyz     = (const float*)d_in[0];
    const float* cov     = (const float*)d_in[1];
    const float* colors  = (const float*)d_in[2];
    const float* opacity = (const float*)d_in[3];
    const float* w2c     = (const float*)d_in[4];
    const float* focal   = (const float*)d_in[5];
    const float* pp      = (const float*)d_in[6];
    const float* bg      = (const float*)d_in[7];
    float* out = (float*)d_out;

    sort_kernel<<<SBLK, 256>>>(xyz, cov, colors, opacity, w2c, focal, pp);
    render_kernel<<<NBLK, NTHR>>>(bg, out);
}